// round 4
// baseline (speedup 1.0000x reference)
#include <cuda_runtime.h>
#include <math_constants.h>

// Problem constants (match reference)
#define POOLK 7
#define NUM_ROIS 300
#define FH 50
#define FW 50
#define FC 512

// Scratch for the channel-reduced feature map (no cudaMalloc allowed)
__device__ float g_fmax[FH * FW];

// ---------------------------------------------------------------------------
// Kernel A: fmax[h][w] = max_c feature_maps[h][w][c]
// One block per (h,w) position; 128 threads, each loads one float4 (4 ch).
// ---------------------------------------------------------------------------
__global__ void __launch_bounds__(128) channel_max_kernel(const float* __restrict__ fm) {
    const int pos = blockIdx.x;               // 0 .. 2499
    const float4* __restrict__ p =
        reinterpret_cast<const float4*>(fm + (size_t)pos * FC);
    float4 v = p[threadIdx.x];                // 128 threads * 4 = 512 channels
    float m = fmaxf(fmaxf(v.x, v.y), fmaxf(v.z, v.w));

    #pragma unroll
    for (int o = 16; o > 0; o >>= 1)
        m = fmaxf(m, __shfl_xor_sync(0xffffffffu, m, o));

    __shared__ float s[4];
    if ((threadIdx.x & 31) == 0) s[threadIdx.x >> 5] = m;
    __syncthreads();
    if (threadIdx.x == 0) {
        m = fmaxf(fmaxf(s[0], s[1]), fmaxf(s[2], s[3]));
        g_fmax[pos] = m;
    }
}

// ---------------------------------------------------------------------------
// Kernel B: per-ROI pooling + broadcast write.
// One block per ROI, 512 threads.
//   1) stage g_fmax (10 KB) into shared
//   2) threads 0..48 compute one bin max each (exact integer-bin formulas)
//   3) all threads stream 49*512 floats as float4 broadcasts
// ---------------------------------------------------------------------------
__global__ void __launch_bounds__(512) roi_pool_kernel(const float* __restrict__ rois,
                                                       float* __restrict__ out) {
    __shared__ float s_fmax[FH * FW];
    __shared__ float s_bin[POOLK * POOLK];

    const int n   = blockIdx.x;
    const int tid = threadIdx.x;

    // Stage the channel-max map (2500 floats)
    for (int i = tid; i < FH * FW; i += 512)
        s_fmax[i] = g_fmax[i];
    __syncthreads();

    if (tid < POOLK * POOLK) {
        // ROI coords: r = int(rois / 16), truncation (rois >= 0 -> floor; /16 exact)
        const float* r = rois + (size_t)n * 5;
        const int x1 = (int)(r[1] * 0.0625f);
        const int y1 = (int)(r[2] * 0.0625f);
        const int x2 = (int)(r[3] * 0.0625f);
        const int y2 = (int)(r[4] * 0.0625f);
        const int rh = y2 - y1 + 1;
        const int rw = x2 - x1 + 1;

        const int bi = tid / POOLK;   // row bin
        const int bj = tid % POOLK;   // col bin

        int hs = y1 + (bi * rh) / POOLK;
        int he = y1 + ((bi + 1) * rh + POOLK - 1) / POOLK;
        int ws = x1 + (bj * rw) / POOLK;
        int we = x1 + ((bj + 1) * rw + POOLK - 1) / POOLK;
        hs = min(max(hs, 0), FH);  he = min(max(he, 0), FH);
        ws = min(max(ws, 0), FW);  we = min(max(we, 0), FW);

        float m = -CUDART_INF_F;
        for (int rr = hs; rr < he; ++rr)
            for (int cc = ws; cc < we; ++cc)
                m = fmaxf(m, s_fmax[rr * FW + cc]);
        s_bin[tid] = m;
    }
    __syncthreads();

    // Broadcast write: 49 bins * 512 ch = 49 * 128 float4 = 6272 float4 per ROI
    float4* __restrict__ o4 =
        reinterpret_cast<float4*>(out + (size_t)n * POOLK * POOLK * FC);
    const int nvec = POOLK * POOLK * (FC / 4);   // 6272
    for (int v = tid; v < nvec; v += 512) {
        const float f = s_bin[v >> 7];           // 128 float4 per bin
        o4[v] = make_float4(f, f, f, f);
    }
}

// ---------------------------------------------------------------------------
extern "C" void kernel_launch(void* const* d_in, const int* in_sizes, int n_in,
                              void* d_out, int out_size) {
    // metadata order: rois (300*5 = 1500), feature_maps (50*50*512 = 1280000).
    // Defend against ordering surprises via element counts.
    const float* rois = (const float*)d_in[0];
    const float* fm   = (const float*)d_in[1];
    if (n_in >= 2 && in_sizes[0] != NUM_ROIS * 5 && in_sizes[1] == NUM_ROIS * 5) {
        rois = (const float*)d_in[1];
        fm   = (const float*)d_in[0];
    }
    float* out = (float*)d_out;

    channel_max_kernel<<<FH * FW, 128>>>(fm);
    roi_pool_kernel<<<NUM_ROIS, 512>>>(rois, out);
}